// round 4
// baseline (speedup 1.0000x reference)
#include <cuda_runtime.h>

// VanillaRNN persistent kernel for GB300 (sm_103a) — round 3: packed f32x2 FMA.
// h_{t+1} = tanh(W_hx * x_t + W_hh @ h_t + b_h), 1024 steps, then p = W_ph @ h + b_p.
//
// 128 persistent CTAs = 16 row-groups x 8 batch-groups, 32x32 output tile each.
//  - W_hh slice stored DUPLICATED in SMEM as (w,w) float2 pairs -> FFMA2 operand
//    with zero runtime packing.
//  - Accumulators packed over column pairs; h operand (h[k][c0],h[k][c0+1]) is a
//    contiguous LDS.64.
//  - h state double-buffered in __device__ global; grid barrier via monotonic atomic.

#define HH    512
#define BB    256
#define TT    1024
#define NCLS  10

#define RGN   16
#define BGN   8
#define HR    32            // rows per CTA
#define BT    32            // batch cols per CTA
#define NCTA  (RGN * BGN)   // 128
#define NTHR  256

#define WD_STRIDE 514       // float2 units per W row (512 + 2 pad) -> 4112B row stride
#define H_PAD     36        // hs row stride in floats (32 + 4)

#define SMEM_FLOATS (HR * WD_STRIDE * 2 + HH * H_PAD + BT)
#define SMEM_BYTES  (SMEM_FLOATS * 4)

typedef unsigned long long u64;

__device__ float    g_h[2][HH][BB];   // double-buffered hidden state
__device__ unsigned g_bar;            // grid barrier counter (memset to 0 per launch)

__device__ __forceinline__ u64 ffma2(u64 a, u64 b, u64 c) {
    u64 d;
    asm("fma.rn.f32x2 %0, %1, %2, %3;" : "=l"(d) : "l"(a), "l"(b), "l"(c));
    return d;
}
__device__ __forceinline__ u64 pack2(float lo, float hi) {
    u64 d;
    asm("mov.b64 %0, {%1, %2};" : "=l"(d) : "f"(lo), "f"(hi));
    return d;
}
__device__ __forceinline__ void unpack2(u64 v, float& lo, float& hi) {
    asm("mov.b64 {%0, %1}, %2;" : "=f"(lo), "=f"(hi) : "l"(v));
}

__global__ void __launch_bounds__(NTHR, 1) rnn_persistent(
    const float* __restrict__ x,       // [BB][TT]
    const float* __restrict__ h_init,  // [HH]
    const float* __restrict__ W_hx,    // [HH]
    const float* __restrict__ W_hh,    // [HH][HH]
    const float* __restrict__ b_h,     // [HH]
    const float* __restrict__ W_ph,    // [NCLS][HH]
    const float* __restrict__ b_p,     // [NCLS]
    float* __restrict__ out)           // [BB][NCLS]
{
    extern __shared__ float smem[];
    float2* Wd = reinterpret_cast<float2*>(smem);      // [HR][WD_STRIDE] dup pairs
    float*  hs = smem + HR * WD_STRIDE * 2;            // [HH][H_PAD]
    float*  xs = hs + HH * H_PAD;                      // [BT]

    const int tid   = threadIdx.x;
    const int cta   = blockIdx.x;
    const int rg    = cta >> 3;
    const int bg    = cta & 7;
    const int rbase = rg * HR;
    const int cbase = bg * BT;

    // ---- build duplicated W slice in SMEM: Wd[r][k] = (w, w) ----
    for (int i = tid; i < HR * HH; i += NTHR) {
        int r = i >> 9;            // /512
        int k = i & 511;
        float w = W_hh[(rbase + r) * HH + k];
        Wd[r * WD_STRIDE + k] = make_float2(w, w);
    }

    // ---- init hs with h_init broadcast ----
    for (int k = tid; k < HH; k += NTHR) {
        float v = h_init[k];
        float* row = hs + k * H_PAD;
        #pragma unroll
        for (int c = 0; c < BT; ++c) row[c] = v;
    }

    // ---- per-thread 2x2 microtile mapping ----
    const int warp = tid >> 5, lane = tid & 31;
    const int wr = warp >> 1, wc = warp & 1;   // 4 x 2 warp grid
    const int rp = lane >> 3, cp = lane & 7;   // 4 row-pairs x 8 col-pairs
    const int r0 = ((wr << 2) + rp) << 1;      // local rows r0, r0+1
    const int c0 = ((wc << 3) + cp) << 1;      // local cols c0, c0+1

    const float bh0 = b_h[rbase + r0];
    const float bh1 = b_h[rbase + r0 + 1];
    const float wx0 = W_hx[rbase + r0];
    const float wx1 = W_hx[rbase + r0 + 1];

    const float2* w0p = Wd + r0 * WD_STRIDE;
    const float2* w1p = w0p + WD_STRIDE;
    const float*  hcp = hs + c0;

    __syncthreads();

    for (int s = 0; s < TT; ++s) {
        // ---- refresh h tile from global ----
        if (s > 0) {
            const int buf = s & 1;
            #pragma unroll
            for (int i = tid; i < HH * (BT / 4); i += NTHR) {
                int k  = i >> 3;
                int cq = i & 7;
                float4 v = __ldcg(reinterpret_cast<const float4*>(
                               &g_h[buf][k][cbase + (cq << 2)]));
                *reinterpret_cast<float4*>(hs + k * H_PAD + (cq << 2)) = v;
            }
        }
        if (tid < BT) xs[tid] = x[(cbase + tid) * TT + s];
        __syncthreads();

        const float xc0 = xs[c0], xc1 = xs[c0 + 1];
        u64 a0 = pack2(fmaf(wx0, xc0, bh0), fmaf(wx0, xc1, bh0));
        u64 a1 = pack2(fmaf(wx1, xc0, bh1), fmaf(wx1, xc1, bh1));

        // ---- 512-deep packed dot products: 2 FFMA2 per k ----
        #pragma unroll 8
        for (int k = 0; k < HH; k += 2) {
            // dup-pair W loads (LDS.128 each: pairs for k and k+1)
            const float4 wa = *reinterpret_cast<const float4*>(w0p + k);
            const float4 wb = *reinterpret_cast<const float4*>(w1p + k);
            // h col-pairs (LDS.64 each)
            const u64 h0 = *reinterpret_cast<const u64*>(hcp + (k + 0) * H_PAD);
            const u64 h1 = *reinterpret_cast<const u64*>(hcp + (k + 1) * H_PAD);
            const u64* wa64 = reinterpret_cast<const u64*>(&wa);
            const u64* wb64 = reinterpret_cast<const u64*>(&wb);
            a0 = ffma2(wa64[0], h0, a0);
            a1 = ffma2(wb64[0], h0, a1);
            a0 = ffma2(wa64[1], h1, a0);
            a1 = ffma2(wb64[1], h1, a1);
        }

        float a00, a01, a10, a11;
        unpack2(a0, a00, a01);
        unpack2(a1, a10, a11);
        a00 = tanhf(a00); a01 = tanhf(a01);
        a10 = tanhf(a10); a11 = tanhf(a11);

        const int wbuf = (s + 1) & 1;
        *reinterpret_cast<float2*>(&g_h[wbuf][rbase + r0    ][cbase + c0]) = make_float2(a00, a01);
        *reinterpret_cast<float2*>(&g_h[wbuf][rbase + r0 + 1][cbase + c0]) = make_float2(a10, a11);

        // ---- grid-wide step barrier ----
        __threadfence();
        __syncthreads();
        if (tid == 0) {
            atomicAdd(&g_bar, 1u);
            const unsigned target = (unsigned)NCTA * (unsigned)(s + 1);
            while (*((volatile unsigned*)&g_bar) < target) { }
            __threadfence();
        }
        __syncthreads();
    }

    // ---- final projection on row-group 0 CTAs ----
    if (rg == 0) {
        float* Wp = smem;  // reuse W region for W_ph (10*512 floats)
        for (int i = tid; i < (NCLS * HH) / 4; i += NTHR) {
            float4 v = *reinterpret_cast<const float4*>(W_ph + (i << 2));
            *reinterpret_cast<float4*>(Wp + (i << 2)) = v;
        }
        for (int i = tid; i < HH * (BT / 4); i += NTHR) {
            int k = i >> 3, cq = i & 7;
            float4 v = __ldcg(reinterpret_cast<const float4*>(
                           &g_h[0][k][cbase + (cq << 2)]));
            *reinterpret_cast<float4*>(hs + k * H_PAD + (cq << 2)) = v;
        }
        __syncthreads();
        for (int idx = tid; idx < BT * NCLS; idx += NTHR) {
            int cl = idx / NCLS;
            int n  = idx - cl * NCLS;
            float acc = b_p[n];
            const float* wrow = Wp + n * HH;
            const float* hcol = hs + cl;
            #pragma unroll 8
            for (int k = 0; k < HH; ++k)
                acc = fmaf(wrow[k], hcol[k * H_PAD], acc);
            out[(cbase + cl) * NCLS + n] = acc;
        }
    }
}

extern "C" void kernel_launch(void* const* d_in, const int* in_sizes, int n_in,
                              void* d_out, int out_size) {
    const float* x      = (const float*)d_in[0];
    const float* h_init = (const float*)d_in[1];
    const float* W_hx   = (const float*)d_in[2];
    const float* W_hh   = (const float*)d_in[3];
    const float* b_h    = (const float*)d_in[4];
    const float* W_ph   = (const float*)d_in[5];
    const float* b_p    = (const float*)d_in[6];
    float* out = (float*)d_out;

    void* barp = nullptr;
    cudaGetSymbolAddress(&barp, g_bar);
    cudaMemsetAsync(barp, 0, sizeof(unsigned), 0);

    cudaFuncSetAttribute(rnn_persistent,
                         cudaFuncAttributeMaxDynamicSharedMemorySize, SMEM_BYTES);

    rnn_persistent<<<NCTA, NTHR, SMEM_BYTES, 0>>>(x, h_init, W_hx, W_hh, b_h,
                                                  W_ph, b_p, out);
}